// round 1
// baseline (speedup 1.0000x reference)
#include <cuda_runtime.h>

#define NSEQ   512
#define NBATCH 64
#define NHID   1024
#define NCAP   16
#define NDIM   64
#define NSPLIT 4
#define SCHUNK 128   // NSEQ / NSPLIT

// Scratch (device globals — no allocation allowed)
__device__ float g_V[NBATCH * NCAP * NHID];            // 4 MB:  V[b][nc][h]
__device__ float g_Y[NBATCH * NSPLIT * NCAP * NHID];   // 16 MB: Y[b][split][nc][h]

__device__ __forceinline__ float dot4(float4 a, float4 b) {
    return fmaf(a.x, b.x, fmaf(a.y, b.y, fmaf(a.z, b.z, a.w * b.w)));
}
__device__ __forceinline__ void fma4(float4 &a, float4 x, float c) {
    a.x = fmaf(c, x.x, a.x);
    a.y = fmaf(c, x.y, a.y);
    a.z = fmaf(c, x.z, a.z);
    a.w = fmaf(c, x.w, a.w);
}

__device__ __forceinline__ void softmax_store(float* dst, const float* l) {
    float m = l[0];
    #pragma unroll
    for (int i = 1; i < NCAP; ++i) m = fmaxf(m, l[i]);
    float e[NCAP];
    float s = 0.f;
    #pragma unroll
    for (int i = 0; i < NCAP; ++i) { e[i] = __expf(l[i] - m); s += e[i]; }
    float inv = 1.0f / s;
    #pragma unroll
    for (int i = 0; i < NCAP; ++i) dst[i] = e[i] * inv;
}

// One CTA = (batch b, s-chunk of 128). Computes per-s softmax coefficients from
// logits x_s · V[b,nc], then the coefficient-weighted sum of x over the chunk:
//   Y[b][split][nc][h] = sum_s c[s][nc] * x[b,s,h]
// iter==0: V is (implicitly) zero -> c = 1/16 exactly; skip logits entirely.
__global__ void __launch_bounds__(256, 2)
pass_kernel(const float* __restrict__ X, int iter) {
    extern __shared__ float sm[];
    float4* Vsh = reinterpret_cast<float4*>(sm);   // 16 x 256 float4 (64 KB)
    float*  csh = sm + NCAP * NHID;                // 128 x 16 floats (8 KB)

    const int b     = blockIdx.y;
    const int split = blockIdx.x;
    const int t     = threadIdx.x;
    const int lane  = t & 31;
    const int w     = t >> 5;
    const int s0    = split * SCHUNK;
    const float4* X4 = reinterpret_cast<const float4*>(X);

    if (iter > 0) {
        // Load V[b] into shared (16K floats)
        const float4* Vb = reinterpret_cast<const float4*>(g_V) + (size_t)b * (NCAP * NHID / 4);
        for (int i = t; i < NCAP * NHID / 4; i += 256) Vsh[i] = Vb[i];
        __syncthreads();

        // Stage A: each warp handles 16 s-values, 4 at a time (V smem reuse x4).
        for (int q = 0; q < 4; ++q) {
            const int sl = w * 16 + q * 4;
            const float4* xp0 = X4 + ((size_t)(s0 + sl + 0) * NBATCH + b) * (NHID / 4);
            const float4* xp1 = X4 + ((size_t)(s0 + sl + 1) * NBATCH + b) * (NHID / 4);
            const float4* xp2 = X4 + ((size_t)(s0 + sl + 2) * NBATCH + b) * (NHID / 4);
            const float4* xp3 = X4 + ((size_t)(s0 + sl + 3) * NBATCH + b) * (NHID / 4);
            float l0[NCAP], l1[NCAP], l2[NCAP], l3[NCAP];
            #pragma unroll
            for (int nc = 0; nc < NCAP; ++nc) { l0[nc] = 0.f; l1[nc] = 0.f; l2[nc] = 0.f; l3[nc] = 0.f; }

            #pragma unroll 2
            for (int j = 0; j < 8; ++j) {
                const int idx = lane + 32 * j;
                float4 x0 = xp0[idx];
                float4 x1 = xp1[idx];
                float4 x2 = xp2[idx];
                float4 x3 = xp3[idx];
                #pragma unroll
                for (int nc = 0; nc < NCAP; ++nc) {
                    float4 v = Vsh[nc * 256 + idx];
                    l0[nc] += dot4(x0, v);
                    l1[nc] += dot4(x1, v);
                    l2[nc] += dot4(x2, v);
                    l3[nc] += dot4(x3, v);
                }
            }
            // Butterfly reduce all 64 partials across the warp
            #pragma unroll
            for (int off = 16; off > 0; off >>= 1) {
                #pragma unroll
                for (int nc = 0; nc < NCAP; ++nc) {
                    l0[nc] += __shfl_xor_sync(0xffffffffu, l0[nc], off);
                    l1[nc] += __shfl_xor_sync(0xffffffffu, l1[nc], off);
                    l2[nc] += __shfl_xor_sync(0xffffffffu, l2[nc], off);
                    l3[nc] += __shfl_xor_sync(0xffffffffu, l3[nc], off);
                }
            }
            if (lane == 0) {
                softmax_store(csh + (size_t)(sl + 0) * NCAP, l0);
                softmax_store(csh + (size_t)(sl + 1) * NCAP, l1);
                softmax_store(csh + (size_t)(sl + 2) * NCAP, l2);
                softmax_store(csh + (size_t)(sl + 3) * NCAP, l3);
            }
        }
        __syncthreads();
    }

    // Stage B: Y[nc][h] = sum_s c[s][nc] * x[s][h]. Thread t owns float4 column t.
    float4* Y4 = reinterpret_cast<float4*>(g_Y) + (size_t)(b * NSPLIT + split) * (NCAP * NHID / 4);
    const float4* xb = X4 + ((size_t)s0 * NBATCH + b) * (NHID / 4) + t;
    const size_t xstride = (size_t)NBATCH * (NHID / 4);

    if (iter == 0) {
        float4 a = make_float4(0.f, 0.f, 0.f, 0.f);
        for (int s = 0; s < SCHUNK; ++s) {
            float4 x = xb[(size_t)s * xstride];
            a.x += x.x; a.y += x.y; a.z += x.z; a.w += x.w;
        }
        const float c = 1.0f / 16.0f;   // softmax of zeros over 16 capsules (exact)
        a.x *= c; a.y *= c; a.z *= c; a.w *= c;
        #pragma unroll
        for (int nc = 0; nc < NCAP; ++nc) Y4[nc * 256 + t] = a;
    } else {
        float4 acc[NCAP];
        #pragma unroll
        for (int nc = 0; nc < NCAP; ++nc) acc[nc] = make_float4(0.f, 0.f, 0.f, 0.f);
        const float4* c4 = reinterpret_cast<const float4*>(csh);
        #pragma unroll 2
        for (int s = 0; s < SCHUNK; ++s) {
            float4 x = xb[(size_t)s * xstride];
            float4 ca = c4[s * 4 + 0];
            float4 cb = c4[s * 4 + 1];
            float4 cc = c4[s * 4 + 2];
            float4 cd = c4[s * 4 + 3];
            fma4(acc[0],  x, ca.x); fma4(acc[1],  x, ca.y); fma4(acc[2],  x, ca.z); fma4(acc[3],  x, ca.w);
            fma4(acc[4],  x, cb.x); fma4(acc[5],  x, cb.y); fma4(acc[6],  x, cb.z); fma4(acc[7],  x, cb.w);
            fma4(acc[8],  x, cc.x); fma4(acc[9],  x, cc.y); fma4(acc[10], x, cc.z); fma4(acc[11], x, cc.w);
            fma4(acc[12], x, cd.x); fma4(acc[13], x, cd.y); fma4(acc[14], x, cd.z); fma4(acc[15], x, cd.w);
        }
        #pragma unroll
        for (int nc = 0; nc < NCAP; ++nc) Y4[nc * 256 + t] = acc[nc];
    }
}

// One CTA = (capsule nc, group of 8 batches).
//   o_raw[b][dc] = sum_h Y[b][nc][h] * W[h][nc*64+dc]   (sum split partials on load)
//   o = squash(o_raw)
//   iter<3:  V[b][nc][h] (+)= sum_dc W[h][nc*64+dc] * o[b][dc]
//   iter==3: write o to output (B, nc, dc)
__global__ void __launch_bounds__(256)
update_kernel(const float* __restrict__ W, float* __restrict__ Og, int iter) {
    __shared__ float Wsh[64][65];
    __shared__ float ysh[8][64];
    __shared__ float osh[8][64];

    const int nc = blockIdx.x;
    const int b0 = blockIdx.y * 8;
    const int t  = threadIdx.x;
    const int dcx = t & 63;
    const int bl  = t >> 6;   // 0..3 (owns batches bl and bl+4)

    float acc0 = 0.f, acc1 = 0.f;
    for (int h0 = 0; h0 < NHID; h0 += 64) {
        __syncthreads();
        #pragma unroll
        for (int k = 0; k < 16; ++k) {
            int idx = t + k * 256;
            int hh = idx >> 6, dc = idx & 63;
            Wsh[hh][dc] = W[(size_t)(h0 + hh) * (NCAP * NDIM) + nc * NDIM + dc];
        }
        #pragma unroll
        for (int k = 0; k < 2; ++k) {
            int idx = t + k * 256;
            int bb = idx >> 6, hh = idx & 63;
            const float* yp = g_Y + (((size_t)(b0 + bb) * NSPLIT) * NCAP + nc) * NHID + h0 + hh;
            ysh[bb][hh] = yp[0] + yp[NCAP * NHID] + yp[2 * NCAP * NHID] + yp[3 * NCAP * NHID];
        }
        __syncthreads();
        #pragma unroll
        for (int hh = 0; hh < 64; ++hh) {
            float wv = Wsh[hh][dcx];
            acc0 = fmaf(ysh[bl][hh],     wv, acc0);
            acc1 = fmaf(ysh[bl + 4][hh], wv, acc1);
        }
    }
    __syncthreads();
    osh[bl][dcx]     = acc0;
    osh[bl + 4][dcx] = acc1;
    __syncthreads();

    // squash per (b, nc): warp w handles b = w
    const int w = t >> 5, lane = t & 31;
    float v0 = osh[w][lane], v1 = osh[w][lane + 32];
    float s = v0 * v0 + v1 * v1;
    #pragma unroll
    for (int off = 16; off > 0; off >>= 1) s += __shfl_xor_sync(0xffffffffu, s, off);
    float inv = rsqrtf(s + 1e-7f);
    osh[w][lane]      = v0 * inv;
    osh[w][lane + 32] = v1 * inv;
    __syncthreads();

    if (iter == 3) {
        #pragma unroll
        for (int k = 0; k < 2; ++k) {
            int idx = t + k * 256;
            int bb = idx >> 6, dc = idx & 63;
            Og[(size_t)(b0 + bb) * (NCAP * NDIM) + nc * NDIM + dc] = osh[bb][dc];
        }
    } else {
        for (int h0 = 0; h0 < NHID; h0 += 64) {
            __syncthreads();
            #pragma unroll
            for (int k = 0; k < 16; ++k) {
                int idx = t + k * 256;
                int hh = idx >> 6, dc = idx & 63;
                Wsh[hh][dc] = W[(size_t)(h0 + hh) * (NCAP * NDIM) + nc * NDIM + dc];
            }
            __syncthreads();
            const int hh2 = t & 63;
            const int blv = t >> 6;
            float a0 = 0.f, a1 = 0.f;
            #pragma unroll
            for (int dc = 0; dc < 64; ++dc) {
                float wv = Wsh[hh2][dc];
                a0 = fmaf(wv, osh[blv][dc],     a0);
                a1 = fmaf(wv, osh[blv + 4][dc], a1);
            }
            float* vp0 = g_V + ((size_t)(b0 + blv) * NCAP + nc) * NHID + h0 + hh2;
            float* vp1 = g_V + ((size_t)(b0 + blv + 4) * NCAP + nc) * NHID + h0 + hh2;
            if (iter == 0) { *vp0 = a0;  *vp1 = a1;  }
            else           { *vp0 += a0; *vp1 += a1; }
        }
    }
}

extern "C" void kernel_launch(void* const* d_in, const int* in_sizes, int n_in,
                              void* d_out, int out_size) {
    (void)n_in; (void)out_size;
    const float* X = (const float*)d_in[0];
    const float* W = (const float*)d_in[1];
    // Defensive: inputs is 512*64*1024 = 33554432 elems, W is 1024*1024 = 1048576.
    if (in_sizes[0] == NHID * NCAP * NDIM) { const float* tmp = X; X = W; W = tmp; }

    cudaFuncSetAttribute(pass_kernel, cudaFuncAttributeMaxDynamicSharedMemorySize, 73728);

    float* out = (float*)d_out;
    for (int iter = 0; iter < 4; ++iter) {
        pass_kernel<<<dim3(NSPLIT, NBATCH), 256, 73728>>>(X, iter);
        update_kernel<<<dim3(NCAP, NBATCH / 8), 256>>>(W, out, iter);
    }
}

// round 2
// speedup vs baseline: 1.3371x; 1.3371x over previous
#include <cuda_runtime.h>

#define NSEQ   512
#define NBATCH 64
#define NHID   1024
#define NCAP   16
#define NDIM   64
#define NSPLIT 4
#define SCHUNK 128   // NSEQ / NSPLIT
#define NPART  16    // h-split for update GEMMs (1024/64)

typedef unsigned long long u64;

// Scratch (device globals — no allocation allowed)
__device__ float g_V[NBATCH * NCAP * NHID];                  // 4 MB:  V[b][nc][h]
__device__ float g_Y[NBATCH * NSPLIT * NCAP * NHID];         // 16 MB: Y[b][split][nc][h]
__device__ float g_opart[NPART * NBATCH * NCAP * NDIM];      // 4 MB:  opart[p][b][nc][dc]
__device__ float g_O[NBATCH * NCAP * NDIM];                  // 256 KB: o[b][nc][dc]

__device__ __forceinline__ float dot4(float4 a, float4 b) {
    return fmaf(a.x, b.x, fmaf(a.y, b.y, fmaf(a.z, b.z, a.w * b.w)));
}
__device__ __forceinline__ void fma4(float4 &a, float4 x, float c) {
    a.x = fmaf(c, x.x, a.x);
    a.y = fmaf(c, x.y, a.y);
    a.z = fmaf(c, x.z, a.z);
    a.w = fmaf(c, x.w, a.w);
}

// Packed fp32x2 ops (FFMA2 — only reachable via PTX)
__device__ __forceinline__ u64 pack2(float lo, float hi) {
    u64 r; asm("mov.b64 %0, {%1, %2};" : "=l"(r) : "f"(lo), "f"(hi)); return r;
}
__device__ __forceinline__ void unpack2(u64 v, float &lo, float &hi) {
    asm("mov.b64 {%0, %1}, %2;" : "=f"(lo), "=f"(hi) : "l"(v));
}
__device__ __forceinline__ u64 ffma2(u64 a, u64 b, u64 c) {
    u64 d; asm("fma.rn.f32x2 %0, %1, %2, %3;" : "=l"(d) : "l"(a), "l"(b), "l"(c)); return d;
}

__device__ __forceinline__ void softmax_store(float* dst, const float* l) {
    float m = l[0];
    #pragma unroll
    for (int i = 1; i < NCAP; ++i) m = fmaxf(m, l[i]);
    float e[NCAP];
    float s = 0.f;
    #pragma unroll
    for (int i = 0; i < NCAP; ++i) { e[i] = __expf(l[i] - m); s += e[i]; }
    float inv = 1.0f / s;
    #pragma unroll
    for (int i = 0; i < NCAP; ++i) dst[i] = e[i] * inv;
}

// One CTA = (batch b, s-chunk of 128). Computes per-s softmax coefficients from
// logits x_s · V[b,nc], then the coefficient-weighted sum of x over the chunk:
//   Y[b][split][nc][h] = sum_s c[s][nc] * x[b,s,h]
// iter==0: V is (implicitly) zero -> c = 1/16 exactly; skip logits entirely.
__global__ void __launch_bounds__(256, 2)
pass_kernel(const float* __restrict__ X, int iter) {
    extern __shared__ float sm[];
    float4* Vsh = reinterpret_cast<float4*>(sm);   // 16 x 256 float4 (64 KB)
    float*  csh = sm + NCAP * NHID;                // 128 x 16 floats (8 KB)

    const int b     = blockIdx.y;
    const int split = blockIdx.x;
    const int t     = threadIdx.x;
    const int lane  = t & 31;
    const int w     = t >> 5;
    const int s0    = split * SCHUNK;
    const float4* X4 = reinterpret_cast<const float4*>(X);

    if (iter > 0) {
        // Load V[b] into shared (16K floats)
        const float4* Vb = reinterpret_cast<const float4*>(g_V) + (size_t)b * (NCAP * NHID / 4);
        for (int i = t; i < NCAP * NHID / 4; i += 256) Vsh[i] = Vb[i];
        __syncthreads();

        // Stage A: each warp handles 16 s-values, 4 at a time (V smem reuse x4).
        for (int q = 0; q < 4; ++q) {
            const int sl = w * 16 + q * 4;
            const float4* xp0 = X4 + ((size_t)(s0 + sl + 0) * NBATCH + b) * (NHID / 4);
            const float4* xp1 = X4 + ((size_t)(s0 + sl + 1) * NBATCH + b) * (NHID / 4);
            const float4* xp2 = X4 + ((size_t)(s0 + sl + 2) * NBATCH + b) * (NHID / 4);
            const float4* xp3 = X4 + ((size_t)(s0 + sl + 3) * NBATCH + b) * (NHID / 4);
            float l0[NCAP], l1[NCAP], l2[NCAP], l3[NCAP];
            #pragma unroll
            for (int nc = 0; nc < NCAP; ++nc) { l0[nc] = 0.f; l1[nc] = 0.f; l2[nc] = 0.f; l3[nc] = 0.f; }

            #pragma unroll 2
            for (int j = 0; j < 8; ++j) {
                const int idx = lane + 32 * j;
                float4 x0 = xp0[idx];
                float4 x1 = xp1[idx];
                float4 x2 = xp2[idx];
                float4 x3 = xp3[idx];
                #pragma unroll
                for (int nc = 0; nc < NCAP; ++nc) {
                    float4 v = Vsh[nc * 256 + idx];
                    l0[nc] += dot4(x0, v);
                    l1[nc] += dot4(x1, v);
                    l2[nc] += dot4(x2, v);
                    l3[nc] += dot4(x3, v);
                }
            }
            // Butterfly reduce all 64 partials across the warp
            #pragma unroll
            for (int off = 16; off > 0; off >>= 1) {
                #pragma unroll
                for (int nc = 0; nc < NCAP; ++nc) {
                    l0[nc] += __shfl_xor_sync(0xffffffffu, l0[nc], off);
                    l1[nc] += __shfl_xor_sync(0xffffffffu, l1[nc], off);
                    l2[nc] += __shfl_xor_sync(0xffffffffu, l2[nc], off);
                    l3[nc] += __shfl_xor_sync(0xffffffffu, l3[nc], off);
                }
            }
            if (lane == 0) {
                softmax_store(csh + (size_t)(sl + 0) * NCAP, l0);
                softmax_store(csh + (size_t)(sl + 1) * NCAP, l1);
                softmax_store(csh + (size_t)(sl + 2) * NCAP, l2);
                softmax_store(csh + (size_t)(sl + 3) * NCAP, l3);
            }
        }
        __syncthreads();
    }

    // Stage B: Y[nc][h] = sum_s c[s][nc] * x[s][h]. Thread t owns float4 column t.
    float4* Y4 = reinterpret_cast<float4*>(g_Y) + (size_t)(b * NSPLIT + split) * (NCAP * NHID / 4);
    const float4* xb = X4 + ((size_t)s0 * NBATCH + b) * (NHID / 4) + t;
    const size_t xstride = (size_t)NBATCH * (NHID / 4);

    if (iter == 0) {
        float4 a = make_float4(0.f, 0.f, 0.f, 0.f);
        for (int s = 0; s < SCHUNK; ++s) {
            float4 x = xb[(size_t)s * xstride];
            a.x += x.x; a.y += x.y; a.z += x.z; a.w += x.w;
        }
        const float c = 1.0f / 16.0f;   // softmax of zeros over 16 capsules (exact)
        a.x *= c; a.y *= c; a.z *= c; a.w *= c;
        #pragma unroll
        for (int nc = 0; nc < NCAP; ++nc) Y4[nc * 256 + t] = a;
    } else {
        // Packed f32x2 accumulation: acc[nc] covers the thread's 4 h-columns as 2 pairs.
        u64 acc[NCAP][2];
        #pragma unroll
        for (int nc = 0; nc < NCAP; ++nc) { acc[nc][0] = 0ull; acc[nc][1] = 0ull; }
        const float4* c4 = reinterpret_cast<const float4*>(csh);
        #pragma unroll 2
        for (int s = 0; s < SCHUNK; ++s) {
            ulonglong2 xv = *reinterpret_cast<const ulonglong2*>(xb + (size_t)s * xstride);
            float4 ca = c4[s * 4 + 0];
            float4 cb = c4[s * 4 + 1];
            float4 cc = c4[s * 4 + 2];
            float4 cd = c4[s * 4 + 3];
            u64 p;
            p = pack2(ca.x, ca.x); acc[0][0]  = ffma2(xv.x, p, acc[0][0]);  acc[0][1]  = ffma2(xv.y, p, acc[0][1]);
            p = pack2(ca.y, ca.y); acc[1][0]  = ffma2(xv.x, p, acc[1][0]);  acc[1][1]  = ffma2(xv.y, p, acc[1][1]);
            p = pack2(ca.z, ca.z); acc[2][0]  = ffma2(xv.x, p, acc[2][0]);  acc[2][1]  = ffma2(xv.y, p, acc[2][1]);
            p = pack2(ca.w, ca.w); acc[3][0]  = ffma2(xv.x, p, acc[3][0]);  acc[3][1]  = ffma2(xv.y, p, acc[3][1]);
            p = pack2(cb.x, cb.x); acc[4][0]  = ffma2(xv.x, p, acc[4][0]);  acc[4][1]  = ffma2(xv.y, p, acc[4][1]);
            p = pack2(cb.y, cb.y); acc[5][0]  = ffma2(xv.x, p, acc[5][0]);  acc[5][1]  = ffma2(xv.y, p, acc[5][1]);
            p = pack2(cb.z, cb.z); acc[6][0]  = ffma2(xv.x, p, acc[6][0]);  acc[6][1]  = ffma2(xv.y, p, acc[6][1]);
            p = pack2(cb.w, cb.w); acc[7][0]  = ffma2(xv.x, p, acc[7][0]);  acc[7][1]  = ffma2(xv.y, p, acc[7][1]);
            p = pack2(cc.x, cc.x); acc[8][0]  = ffma2(xv.x, p, acc[8][0]);  acc[8][1]  = ffma2(xv.y, p, acc[8][1]);
            p = pack2(cc.y, cc.y); acc[9][0]  = ffma2(xv.x, p, acc[9][0]);  acc[9][1]  = ffma2(xv.y, p, acc[9][1]);
            p = pack2(cc.z, cc.z); acc[10][0] = ffma2(xv.x, p, acc[10][0]); acc[10][1] = ffma2(xv.y, p, acc[10][1]);
            p = pack2(cc.w, cc.w); acc[11][0] = ffma2(xv.x, p, acc[11][0]); acc[11][1] = ffma2(xv.y, p, acc[11][1]);
            p = pack2(cd.x, cd.x); acc[12][0] = ffma2(xv.x, p, acc[12][0]); acc[12][1] = ffma2(xv.y, p, acc[12][1]);
            p = pack2(cd.y, cd.y); acc[13][0] = ffma2(xv.x, p, acc[13][0]); acc[13][1] = ffma2(xv.y, p, acc[13][1]);
            p = pack2(cd.z, cd.z); acc[14][0] = ffma2(xv.x, p, acc[14][0]); acc[14][1] = ffma2(xv.y, p, acc[14][1]);
            p = pack2(cd.w, cd.w); acc[15][0] = ffma2(xv.x, p, acc[15][0]); acc[15][1] = ffma2(xv.y, p, acc[15][1]);
        }
        #pragma unroll
        for (int nc = 0; nc < NCAP; ++nc) {
            float4 r;
            unpack2(acc[nc][0], r.x, r.y);
            unpack2(acc[nc][1], r.z, r.w);
            Y4[nc * 256 + t] = r;
        }
    }
}

// U1: partial projection. CTA = (nc, h-part p of 64).
//   opart[p][b][nc][dc] = sum_{hh in part} (sum_splits Y[b][split][nc][h]) * W[h][nc*64+dc]
__global__ void __launch_bounds__(256)
u1_kernel(const float* __restrict__ W) {
    __shared__ float Wsh[64 * 64];   // [hh][dc]
    __shared__ float ysh[64 * 65];   // [b][hh] (padded)

    const int nc = blockIdx.x;
    const int p  = blockIdx.y;
    const int h0 = p * 64;
    const int t  = threadIdx.x;

    #pragma unroll
    for (int k = 0; k < 16; ++k) {
        int idx = t + k * 256;
        int hh = idx >> 6, dc = idx & 63;
        Wsh[hh * 64 + dc] = W[(size_t)(h0 + hh) * (NCAP * NDIM) + nc * NDIM + dc];
    }
    #pragma unroll
    for (int k = 0; k < 16; ++k) {
        int idx = t + k * 256;
        int b = idx >> 6, hh = idx & 63;
        const float* yp = g_Y + (((size_t)b * NSPLIT) * NCAP + nc) * NHID + h0 + hh;
        ysh[b * 65 + hh] = yp[0] + yp[NCAP * NHID] + yp[2 * NCAP * NHID] + yp[3 * NCAP * NHID];
    }
    __syncthreads();

    const int dc4  = (t & 15) * 4;
    const int brow = (t >> 4) * 4;
    float4 a0 = make_float4(0,0,0,0), a1 = a0, a2 = a0, a3 = a0;
    #pragma unroll 4
    for (int hh = 0; hh < 64; ++hh) {
        float4 w4 = *reinterpret_cast<const float4*>(&Wsh[hh * 64 + dc4]);
        fma4(a0, w4, ysh[(brow + 0) * 65 + hh]);
        fma4(a1, w4, ysh[(brow + 1) * 65 + hh]);
        fma4(a2, w4, ysh[(brow + 2) * 65 + hh]);
        fma4(a3, w4, ysh[(brow + 3) * 65 + hh]);
    }
    float4* dst0 = reinterpret_cast<float4*>(g_opart + (((size_t)p * NBATCH + brow + 0) * NCAP + nc) * NDIM + dc4);
    float4* dst1 = reinterpret_cast<float4*>(g_opart + (((size_t)p * NBATCH + brow + 1) * NCAP + nc) * NDIM + dc4);
    float4* dst2 = reinterpret_cast<float4*>(g_opart + (((size_t)p * NBATCH + brow + 2) * NCAP + nc) * NDIM + dc4);
    float4* dst3 = reinterpret_cast<float4*>(g_opart + (((size_t)p * NBATCH + brow + 3) * NCAP + nc) * NDIM + dc4);
    *dst0 = a0; *dst1 = a1; *dst2 = a2; *dst3 = a3;
}

// Squash: sum 16 h-partials, normalize per (b,nc). CTA = b; thread = (nc, dc-quad).
__global__ void __launch_bounds__(256)
squash_kernel(float* __restrict__ Og, int last) {
    const int b = blockIdx.x;
    const int t = threadIdx.x;
    const int nc = t >> 4;
    const int q  = t & 15;

    float4 a = make_float4(0,0,0,0);
    #pragma unroll
    for (int p = 0; p < NPART; ++p) {
        const float4* src = reinterpret_cast<const float4*>(
            g_opart + (((size_t)p * NBATCH + b) * NCAP + nc) * NDIM) + q;
        float4 v = *src;
        a.x += v.x; a.y += v.y; a.z += v.z; a.w += v.w;
    }
    float ss = a.x * a.x + a.y * a.y + a.z * a.z + a.w * a.w;
    #pragma unroll
    for (int off = 8; off > 0; off >>= 1) ss += __shfl_xor_sync(0xffffffffu, ss, off);
    float inv = rsqrtf(ss + 1e-7f);
    a.x *= inv; a.y *= inv; a.z *= inv; a.w *= inv;

    float4* dst = reinterpret_cast<float4*>(g_O + ((size_t)b * NCAP + nc) * NDIM) + q;
    *dst = a;
    if (last) {
        float4* o = reinterpret_cast<float4*>(Og + ((size_t)b * NCAP + nc) * NDIM) + q;
        *o = a;
    }
}

// U2: V rank-update. CTA = (nc, h-part p of 64).
//   V[b][nc][h0+hh] (+)= sum_dc W[h0+hh][nc*64+dc] * o[b][nc][dc]
__global__ void __launch_bounds__(256)
u2_kernel(const float* __restrict__ W, int iter) {
    __shared__ float WshT[64 * 68];  // [dc][hh] (transposed, padded)
    __shared__ float osh[64 * 64];   // [b][dc]

    const int nc = blockIdx.x;
    const int p  = blockIdx.y;
    const int h0 = p * 64;
    const int t  = threadIdx.x;

    #pragma unroll
    for (int k = 0; k < 16; ++k) {
        int idx = t + k * 256;
        int hh = idx >> 6, dc = idx & 63;
        WshT[dc * 68 + hh] = W[(size_t)(h0 + hh) * (NCAP * NDIM) + nc * NDIM + dc];
    }
    #pragma unroll
    for (int k = 0; k < 16; ++k) {
        int idx = t + k * 256;
        int b = idx >> 6, dc = idx & 63;
        osh[b * 64 + dc] = g_O[((size_t)b * NCAP + nc) * NDIM + dc];
    }
    __syncthreads();

    const int hh4  = (t & 15) * 4;
    const int brow = (t >> 4) * 4;
    float4 a0 = make_float4(0,0,0,0), a1 = a0, a2 = a0, a3 = a0;
    #pragma unroll 4
    for (int dc = 0; dc < 64; ++dc) {
        float4 w4 = *reinterpret_cast<const float4*>(&WshT[dc * 68 + hh4]);
        fma4(a0, w4, osh[(brow + 0) * 64 + dc]);
        fma4(a1, w4, osh[(brow + 1) * 64 + dc]);
        fma4(a2, w4, osh[(brow + 2) * 64 + dc]);
        fma4(a3, w4, osh[(brow + 3) * 64 + dc]);
    }
    #pragma unroll
    for (int i = 0; i < 4; ++i) {
        float4 a = (i == 0) ? a0 : (i == 1) ? a1 : (i == 2) ? a2 : a3;
        float4* vp = reinterpret_cast<float4*>(
            g_V + (((size_t)(brow + i)) * NCAP + nc) * NHID + h0 + hh4);
        if (iter == 0) {
            *vp = a;
        } else {
            float4 old = *vp;
            old.x += a.x; old.y += a.y; old.z += a.z; old.w += a.w;
            *vp = old;
        }
    }
}

extern "C" void kernel_launch(void* const* d_in, const int* in_sizes, int n_in,
                              void* d_out, int out_size) {
    (void)n_in; (void)out_size;
    const float* X = (const float*)d_in[0];
    const float* W = (const float*)d_in[1];
    if (in_sizes[0] == NHID * NCAP * NDIM) { const float* tmp = X; X = W; W = tmp; }

    cudaFuncSetAttribute(pass_kernel, cudaFuncAttributeMaxDynamicSharedMemorySize, 73728);

    float* out = (float*)d_out;
    for (int iter = 0; iter < 4; ++iter) {
        pass_kernel<<<dim3(NSPLIT, NBATCH), 256, 73728>>>(X, iter);
        u1_kernel<<<dim3(NCAP, NPART), 256>>>(W);
        squash_kernel<<<NBATCH, 256>>>(out, iter == 3 ? 1 : 0);
        if (iter < 3) u2_kernel<<<dim3(NCAP, NPART), 256>>>(W, iter);
    }
}